// round 4
// baseline (speedup 1.0000x reference)
#include <cuda_runtime.h>
#include <math.h>
#include <cstdint>

#define B_   128
#define T_   512
#define D_   256
#define H_   512
#define G4_  2048   // 4*H

// ---- static device scratch ----
__device__ float g_xp[(size_t)T_ * B_ * G4_];   // [T*B, 4H] x-projections (+biases)
__device__ float g_xr[(size_t)B_ * T_ * D_];    // tf32-rounded x
__device__ float g_wr[(size_t)G4_ * D_];        // tf32-rounded W_ih
__device__ float g_h[2][B_ * H_];               // ping-pong h, PAIRED-FRAGMENT layout
__device__ unsigned g_count = 0;
__device__ volatile unsigned g_gen = 0;

// =====================================================================
// helpers
// =====================================================================
__device__ __forceinline__ float tf32r(float x) {
    float y; asm("cvt.rna.tf32.f32 %0, %1;" : "=f"(y) : "f"(x)); return y;
}
__device__ __forceinline__ uint32_t smem_u32(const void* p) {
    uint32_t a;
    asm("{ .reg .u64 t; cvta.to.shared.u64 t, %1; cvt.u32.u64 %0, t; }" : "=r"(a) : "l"(p));
    return a;
}
__device__ __forceinline__ void cp16(uint32_t dst, const void* src) {
    asm volatile("cp.async.ca.shared.global [%0], [%1], 16;" :: "r"(dst), "l"(src));
}
#define CP_COMMIT() asm volatile("cp.async.commit_group;" ::: "memory")
#define CP_WAIT1()  asm volatile("cp.async.wait_group 1;" ::: "memory")
#define CP_WAIT0()  asm volatile("cp.async.wait_group 0;" ::: "memory")

__device__ __forceinline__ void mma1688(float* c, const uint32_t* a, const uint32_t* b) {
    asm volatile(
        "mma.sync.aligned.m16n8k8.row.col.f32.tf32.tf32.f32 "
        "{%0,%1,%2,%3}, {%4,%5,%6,%7}, {%8,%9}, {%0,%1,%2,%3};"
        : "+f"(c[0]), "+f"(c[1]), "+f"(c[2]), "+f"(c[3])
        : "r"(a[0]), "r"(a[1]), "r"(a[2]), "r"(a[3]), "r"(b[0]), "r"(b[1]));
}
__device__ __forceinline__ float fcomp(const float4& v, int i) {
    return i == 0 ? v.x : (i == 1 ? v.y : (i == 2 ? v.z : v.w));
}

__device__ __forceinline__ void grid_barrier(int step, unsigned ncta)
{
    __syncthreads();
    if (threadIdx.x == 0) {
        unsigned next = (unsigned)((step + 1) & (T_ - 1));
        __threadfence();
        unsigned old = atomicAdd(&g_count, 1u);
        if (old == ncta - 1u) {
            g_count = 0;
            __threadfence();
            g_gen = next;
        } else {
            while (g_gen != next) { }
        }
        __threadfence();
    }
    __syncthreads();
}

// =====================================================================
// Kernel 0: tf32 pre-rounding
// =====================================================================
__global__ void __launch_bounds__(256) round_k(const float4* __restrict__ src,
                                               float4* __restrict__ dst, int n4)
{
    int i = blockIdx.x * blockDim.x + threadIdx.x;
    if (i < n4) {
        float4 v = src[i];
        v.x = tf32r(v.x); v.y = tf32r(v.y); v.z = tf32r(v.z); v.w = tf32r(v.w);
        dst[i] = v;
    }
}

// =====================================================================
// Kernel 1: x_proj GEMM, cp.async double-buffered, tf32 mma
//   grid = 512 m-tiles x 32 n-tiles; CTA tile M=128, N=64, K=256 (4 chunks)
//   8 warps, warp tile 32x32
// =====================================================================
#define XA_STR 68
#define XABUF (128 * XA_STR)
#define XBBUF (64 * XA_STR)
#define XP_SMEM ((2 * XABUF + 2 * XBBUF) * 4)

__global__ void __launch_bounds__(256, 2) xproj_mma(
    const float* __restrict__ xr,    // [B*T, D] tf32-rounded
    const float* __restrict__ Wr,    // [4H, D]  tf32-rounded
    const float* __restrict__ bih,
    const float* __restrict__ bhh)
{
    extern __shared__ float sm[];
    float* Abuf[2] = { sm, sm + XABUF };
    float* Bbuf[2] = { sm + 2 * XABUF, sm + 2 * XABUF + XBBUF };
    const uint32_t sb = smem_u32(sm);

    const int tid  = threadIdx.x;
    const int wid  = tid >> 5;
    const int lane = tid & 31;
    const int g    = lane >> 2;
    const int tig  = lane & 3;
    const int wm   = wid & 3;
    const int wcol = (wid >> 2) * 32;

    const int mt = blockIdx.x >> 5;
    const int nt = blockIdx.x & 31;
    const int m0 = mt * 128;
    const int n0 = nt * 64;

    // cp.async issue for chunk kc into buffer s
    const int arow = tid >> 1, ah = (tid & 1) * 32;
    const int brow = tid >> 2, bh = (tid & 3) * 16;

    float c[2][4][4];
#pragma unroll
    for (int a = 0; a < 2; ++a)
#pragma unroll
        for (int b = 0; b < 4; ++b)
#pragma unroll
            for (int i = 0; i < 4; ++i) c[a][b][i] = 0.f;

#pragma unroll
    for (int pre = 0; pre < 2; ++pre) {
        int k0 = pre * 64;
        const float* asrc = xr + (size_t)(m0 + arow) * D_ + k0 + ah;
        uint32_t adst = sb + (uint32_t)(pre * XABUF + arow * XA_STR + ah) * 4;
#pragma unroll
        for (int i = 0; i < 8; ++i) cp16(adst + i * 16, asrc + i * 4);
        const float* bsrc = Wr + (size_t)(n0 + brow) * D_ + k0 + bh;
        uint32_t bdst = sb + (uint32_t)((2 * XABUF + pre * XBBUF) + brow * XA_STR + bh) * 4;
#pragma unroll
        for (int i = 0; i < 4; ++i) cp16(bdst + i * 16, bsrc + i * 4);
        CP_COMMIT();
    }

    for (int kc = 0; kc < 4; ++kc) {
        if (kc < 3) { CP_WAIT1(); } else { CP_WAIT0(); }
        __syncthreads();

        const float* Ash = Abuf[kc & 1];
        const float* Bsh = Bbuf[kc & 1];
        const float* a0p = Ash + (wm * 32 + g) * XA_STR;
        const float* a1p = a0p + 8 * XA_STR;
        const float* a2p = a0p + 16 * XA_STR;
        const float* a3p = a0p + 24 * XA_STR;
        const float* bp0 = Bsh + (wcol + 0  + g) * XA_STR;
        const float* bp1 = Bsh + (wcol + 8  + g) * XA_STR;
        const float* bp2 = Bsh + (wcol + 16 + g) * XA_STR;
        const float* bp3 = Bsh + (wcol + 24 + g) * XA_STR;

#pragma unroll 4
        for (int kk = 0; kk < 8; ++kk) {
            const int k8 = kk * 8 + tig;
            uint32_t af0[4] = { __float_as_uint(a0p[k8]), __float_as_uint(a1p[k8]),
                                __float_as_uint(a0p[k8 + 4]), __float_as_uint(a1p[k8 + 4]) };
            uint32_t af1[4] = { __float_as_uint(a2p[k8]), __float_as_uint(a3p[k8]),
                                __float_as_uint(a2p[k8 + 4]), __float_as_uint(a3p[k8 + 4]) };
            uint32_t bf0[2] = { __float_as_uint(bp0[k8]), __float_as_uint(bp0[k8 + 4]) };
            uint32_t bf1[2] = { __float_as_uint(bp1[k8]), __float_as_uint(bp1[k8 + 4]) };
            uint32_t bf2[2] = { __float_as_uint(bp2[k8]), __float_as_uint(bp2[k8 + 4]) };
            uint32_t bf3[2] = { __float_as_uint(bp3[k8]), __float_as_uint(bp3[k8 + 4]) };
            mma1688(c[0][0], af0, bf0); mma1688(c[0][1], af0, bf1);
            mma1688(c[0][2], af0, bf2); mma1688(c[0][3], af0, bf3);
            mma1688(c[1][0], af1, bf0); mma1688(c[1][1], af1, bf1);
            mma1688(c[1][2], af1, bf2); mma1688(c[1][3], af1, bf3);
        }
        __syncthreads();

        if (kc < 2) {
            int k0 = (kc + 2) * 64;
            int s  = kc & 1;
            const float* asrc = xr + (size_t)(m0 + arow) * D_ + k0 + ah;
            uint32_t adst = sb + (uint32_t)(s * XABUF + arow * XA_STR + ah) * 4;
#pragma unroll
            for (int i = 0; i < 8; ++i) cp16(adst + i * 16, asrc + i * 4);
            const float* bsrc = Wr + (size_t)(n0 + brow) * D_ + k0 + bh;
            uint32_t bdst = sb + (uint32_t)((2 * XABUF + s * XBBUF) + brow * XA_STR + bh) * 4;
#pragma unroll
            for (int i = 0; i < 4; ++i) cp16(bdst + i * 16, bsrc + i * 4);
            CP_COMMIT();
        }
    }

    // epilogue: bias add + remap row (b*T+t -> t*B+b)
    float2 bias[4];
#pragma unroll
    for (int nf = 0; nf < 4; ++nf) {
        int col = n0 + wcol + nf * 8 + 2 * tig;
        bias[nf].x = bih[col] + bhh[col];
        bias[nf].y = bih[col + 1] + bhh[col + 1];
    }
#pragma unroll
    for (int mf = 0; mf < 2; ++mf) {
#pragma unroll
        for (int rs = 0; rs < 2; ++rs) {
            int grow = m0 + wm * 32 + mf * 16 + g + rs * 8;
            int b = grow >> 9;
            int t = grow & 511;
            float* orow = g_xp + ((size_t)t * B_ + b) * G4_ + n0 + wcol + 2 * tig;
#pragma unroll
            for (int nf = 0; nf < 4; ++nf) {
                float2 v;
                v.x = c[mf][nf][rs * 2 + 0] + bias[nf].x;
                v.y = c[mf][nf][rs * 2 + 1] + bias[nf].y;
                *(float2*)(orow + nf * 8) = v;
            }
        }
    }
}

// =====================================================================
// Kernel 2: persistent recurrence, k-split tf32 mma.
//   128 CTAs (4 b-tiles x 32 j-tiles) x 128 threads.
//   Warp w computes full 32x64 tile over K slice [w*128, w*128+128);
//   partials reduced through SMEM. h lives in GLOBAL paired-fragment layout.
//   paired-16 pos(k) = (k>>4)*16 + (k&3)*4 + ((k>>2)&1) + 2*((k>>3)&1)
// =====================================================================
#define WS 520                         // Wsh row stride (floats)
#define PS (32 * 68)                   // one partial tile (floats)
#define REC_SMEM ((64 * WS + 4 * PS) * 4)

__global__ void __launch_bounds__(128, 1) lstm_rec_mma(
    const float* __restrict__ Whh,   // [4H, H]
    float* __restrict__ out)         // [T*B, H]
{
    extern __shared__ float sm[];
    float* Wsh = sm;                 // [64 n][520] paired layout
    float* Psh = sm + 64 * WS;       // 4 x [32][68]

    const int tid  = threadIdx.x;
    const int wid  = tid >> 5;
    const int lane = tid & 31;
    const int g    = lane >> 2;      // 0..7
    const int tq   = lane & 3;       // 0..3
    const int bt = blockIdx.x >> 5;
    const int jt = blockIdx.x & 31;
    const int b0 = bt * 32;
    const int j0 = jt * 16;

    // ---- one-time: W_hh slice -> paired-layout SMEM (tf32-rna) ----
    {
        int n  = tid >> 1;               // 0..63 : n = gate*16 + jl
        int kh = (tid & 1) * 256;
        int gate = n >> 4, jl = n & 15;
        const float* wr = Whh + (size_t)(gate * H_ + j0 + jl) * H_ + kh;
        float* dst = Wsh + n * WS;
#pragma unroll 4
        for (int k = 0; k < 256; k += 4) {
            float4 v = *(const float4*)(wr + k);
            int ka  = kh + k;
            int blk = (ka >> 4) * 16;
            int e   = ((ka >> 2) & 1) + ((ka >> 3) & 1) * 2;
            dst[blk + 0 + e]  = tf32r(v.x);
            dst[blk + 4 + e]  = tf32r(v.y);
            dst[blk + 8 + e]  = tf32r(v.z);
            dst[blk + 12 + e] = tf32r(v.w);
        }
    }
    __syncthreads();

    const int jq   = tq * 4;             // thread's 4 j-cols: jq..jq+3
    const int brow = 8 * wid + g;        // thread's b-row for reduce/cell
    const int kbase = wid * 128;         // warp's K slice
    float c_reg[4] = {0.f, 0.f, 0.f, 0.f};

    for (int t = 0; t < T_; ++t) {
        // xp prefetch for this thread's cell elements (hidden under mma)
        float pf[4][4];
        {
            const float* xb = g_xp + ((size_t)t * B_ + b0 + brow) * G4_ + j0 + jq;
#pragma unroll
            for (int qd = 0; qd < 4; ++qd) {
                float4 v = *(const float4*)(xb + qd * 512);
                pf[qd][0] = v.x; pf[qd][1] = v.y; pf[qd][2] = v.z; pf[qd][3] = v.w;
            }
        }

        float acc[2][8][4];
#pragma unroll
        for (int m2 = 0; m2 < 2; ++m2)
#pragma unroll
            for (int n = 0; n < 8; ++n)
#pragma unroll
                for (int i = 0; i < 4; ++i) acc[m2][n][i] = 0.f;

        if (t > 0) {
            const float* hb = g_h[(t - 1) & 1] + bt * 16384;
#pragma unroll 2
            for (int kk2 = 0; kk2 < 8; ++kk2) {
                const int ko = kbase + kk2 * 16 + jq;   // paired float4 offset
                float4 a4[4];
#pragma unroll
                for (int r = 0; r < 4; ++r)
                    a4[r] = __ldcg((const float4*)(hb + (g + 8 * r) * 512 + ko));
                float4 b4[8];
#pragma unroll
                for (int n = 0; n < 8; ++n)
                    b4[n] = *(const float4*)(Wsh + (g + 8 * n) * WS + ko);
#pragma unroll
                for (int ks = 0; ks < 2; ++ks) {
#pragma unroll
                    for (int m2 = 0; m2 < 2; ++m2) {
                        uint32_t aa[4] = {
                            __float_as_uint(fcomp(a4[2 * m2],     2 * ks)),
                            __float_as_uint(fcomp(a4[2 * m2 + 1], 2 * ks)),
                            __float_as_uint(fcomp(a4[2 * m2],     2 * ks + 1)),
                            __float_as_uint(fcomp(a4[2 * m2 + 1], 2 * ks + 1)) };
#pragma unroll
                        for (int n = 0; n < 8; ++n) {
                            uint32_t bb[2] = {
                                __float_as_uint(fcomp(b4[n], 2 * ks)),
                                __float_as_uint(fcomp(b4[n], 2 * ks + 1)) };
                            mma1688(acc[m2][n], aa, bb);
                        }
                    }
                }
            }
        }

        // store partials to SMEM
        {
            float* P = Psh + wid * PS;
#pragma unroll
            for (int m2 = 0; m2 < 2; ++m2)
#pragma unroll
                for (int n = 0; n < 8; ++n) {
                    float2 v0; v0.x = acc[m2][n][0]; v0.y = acc[m2][n][1];
                    float2 v1; v1.x = acc[m2][n][2]; v1.y = acc[m2][n][3];
                    *(float2*)(P + (m2 * 16 + g) * 68 + n * 8 + 2 * tq)     = v0;
                    *(float2*)(P + (m2 * 16 + 8 + g) * 68 + n * 8 + 2 * tq) = v1;
                }
        }
        __syncthreads();

        // reduce 4 partials for this thread's (brow, jq..jq+3, 4 gates) + xp
        float s[4][4];
#pragma unroll
        for (int qd = 0; qd < 4; ++qd)
#pragma unroll
            for (int i = 0; i < 4; ++i) s[qd][i] = pf[qd][i];
#pragma unroll
        for (int p = 0; p < 4; ++p) {
            const float* Pp = Psh + p * PS + brow * 68 + jq;
#pragma unroll
            for (int qd = 0; qd < 4; ++qd) {
                float4 v = *(const float4*)(Pp + qd * 16);
                s[qd][0] += v.x; s[qd][1] += v.y; s[qd][2] += v.z; s[qd][3] += v.w;
            }
        }

        // fused LSTM cell (gate order i,f,g,o)
        float hv[4];
#pragma unroll
        for (int i = 0; i < 4; ++i) {
            float i_s = 1.f / (1.f + __expf(-s[0][i]));
            float f_s = 1.f / (1.f + __expf(-s[1][i]));
            float g_t = tanhf(s[2][i]);
            float o_s = 1.f / (1.f + __expf(-s[3][i]));
            float cv  = f_s * c_reg[i] + i_s * g_t;
            c_reg[i]  = cv;
            hv[i]     = o_s * tanhf(cv);
        }

        // output store (row-major)
        {
            float* op = out + ((size_t)t * B_ + b0 + brow) * H_ + j0 + jq;
            float4 o; o.x = hv[0]; o.y = hv[1]; o.z = hv[2]; o.w = hv[3];
            *(float4*)op = o;
        }
        // h store, paired-fragment layout: pos(j=jq+i) = 4*i + tq within 16-block
        {
            float* hp = g_h[t & 1] + bt * 16384 + (size_t)brow * 512 + jt * 16;
#pragma unroll
            for (int i = 0; i < 4; ++i) hp[4 * i + tq] = tf32r(hv[i]);
        }

        grid_barrier(t, 128u);   // also protects Psh reuse across steps
    }
}

// =====================================================================
extern "C" void kernel_launch(void* const* d_in, const int* in_sizes, int n_in,
                              void* d_out, int out_size)
{
    const float* x   = (const float*)d_in[0];   // [B,T,D]
    const float* Wih = (const float*)d_in[1];   // [4H,D]
    const float* Whh = (const float*)d_in[2];   // [4H,H]
    const float* bih = (const float*)d_in[3];   // [4H]
    const float* bhh = (const float*)d_in[4];   // [4H]
    float* out = (float*)d_out;

    float* xr; cudaGetSymbolAddress((void**)&xr, g_xr);
    float* wr; cudaGetSymbolAddress((void**)&wr, g_wr);

    // Phase 0: tf32 pre-rounding (enables cp.async staging in xproj)
    round_k<<<(B_ * T_ * D_ / 4 + 255) / 256, 256>>>((const float4*)x, (float4*)xr, B_ * T_ * D_ / 4);
    round_k<<<(G4_ * D_ / 4 + 255) / 256, 256>>>((const float4*)Wih, (float4*)wr, G4_ * D_ / 4);

    // Phase 1: input projections
    cudaFuncSetAttribute(xproj_mma,
                         cudaFuncAttributeMaxDynamicSharedMemorySize, XP_SMEM);
    xproj_mma<<<16384, 256, XP_SMEM>>>(xr, wr, bih, bhh);

    // Phase 2: persistent recurrence
    cudaFuncSetAttribute(lstm_rec_mma,
                         cudaFuncAttributeMaxDynamicSharedMemorySize, REC_SMEM);
    lstm_rec_mma<<<128, 128, REC_SMEM>>>(Whh, out);
}

// round 5
// speedup vs baseline: 1.3224x; 1.3224x over previous
#include <cuda_runtime.h>
#include <math.h>
#include <cstdint>

#define B_   128
#define T_   512
#define D_   256
#define H_   512
#define G4_  2048   // 4*H

// ---- static device scratch ----
__device__ float g_xp[(size_t)T_ * B_ * G4_];   // [T*B, 4H] x-projections (+biases)
__device__ float g_h[2][B_ * H_];               // ping-pong h, PAIRED-FRAGMENT layout per row
__device__ unsigned g_count = 0;
__device__ volatile unsigned g_gen = 0;

// =====================================================================
// helpers
// =====================================================================
__device__ __forceinline__ float tf32r(float x) {
    float y; asm("cvt.rna.tf32.f32 %0, %1;" : "=f"(y) : "f"(x)); return y;
}
__device__ __forceinline__ uint32_t smem_u32(const void* p) {
    uint32_t a;
    asm("{ .reg .u64 t; cvta.to.shared.u64 t, %1; cvt.u32.u64 %0, t; }" : "=r"(a) : "l"(p));
    return a;
}
__device__ __forceinline__ void mma1688(float* c, const uint32_t* a, const uint32_t* b) {
    asm volatile(
        "mma.sync.aligned.m16n8k8.row.col.f32.tf32.tf32.f32 "
        "{%0,%1,%2,%3}, {%4,%5,%6,%7}, {%8,%9}, {%0,%1,%2,%3};"
        : "+f"(c[0]), "+f"(c[1]), "+f"(c[2]), "+f"(c[3])
        : "r"(a[0]), "r"(a[1]), "r"(a[2]), "r"(a[3]), "r"(b[0]), "r"(b[1]));
}
__device__ __forceinline__ float fcomp(const float4& v, int i) {
    return i == 0 ? v.x : (i == 1 ? v.y : (i == 2 ? v.z : v.w));
}

__device__ __forceinline__ void grid_barrier(int step, unsigned ncta)
{
    __syncthreads();
    if (threadIdx.x == 0) {
        unsigned next = (unsigned)((step + 1) & (T_ - 1));
        __threadfence();
        unsigned old = atomicAdd(&g_count, 1u);
        if (old == ncta - 1u) {
            g_count = 0;
            __threadfence();
            g_gen = next;
        } else {
            while (g_gen != next) { }
        }
        __threadfence();
    }
    __syncthreads();
}

// =====================================================================
// Kernel 1: x_proj GEMM via tf32 mma (round-3 proven version)
//   grid = 512 m-tiles x 32 n-tiles; CTA tile M=128, N=64, K=256 (4 chunks)
// =====================================================================
#define XA_STR 68
#define XB_STR 68
#define XP_SMEM ((128 * XA_STR + 64 * XB_STR) * 4)

__global__ void __launch_bounds__(256, 1) xproj_mma(
    const float* __restrict__ x,     // [B*T, D]
    const float* __restrict__ Wih,   // [4H, D]
    const float* __restrict__ bih,
    const float* __restrict__ bhh)
{
    extern __shared__ float sm[];
    float* Ash = sm;                   // [128][68]
    float* Bsh = sm + 128 * XA_STR;    // [64][68]

    const int tid  = threadIdx.x;
    const int wid  = tid >> 5;
    const int lane = tid & 31;
    const int g    = lane >> 2;
    const int tig  = lane & 3;
    const int wm   = wid & 3;
    const int wcol = (wid >> 2) * 32;

    const int mt = blockIdx.x >> 5;
    const int nt = blockIdx.x & 31;
    const int m0 = mt * 128;
    const int n0 = nt * 64;

    float c[2][4][4];
#pragma unroll
    for (int a = 0; a < 2; ++a)
#pragma unroll
        for (int b = 0; b < 4; ++b)
#pragma unroll
            for (int i = 0; i < 4; ++i) c[a][b][i] = 0.f;

    for (int kc = 0; kc < 4; ++kc) {
        const int k0 = kc * 64;
        __syncthreads();
        {
            int row = tid >> 1;
            int h   = (tid & 1) * 32;
            const float* src = x + (size_t)(m0 + row) * D_ + k0 + h;
            float* dst = Ash + row * XA_STR + h;
#pragma unroll
            for (int i = 0; i < 8; ++i) {
                float4 v = *(const float4*)(src + i * 4);
                v.x = tf32r(v.x); v.y = tf32r(v.y); v.z = tf32r(v.z); v.w = tf32r(v.w);
                *(float4*)(dst + i * 4) = v;
            }
        }
        {
            int n = tid >> 2;
            int h = (tid & 3) * 16;
            const float* src = Wih + (size_t)(n0 + n) * D_ + k0 + h;
            float* dst = Bsh + n * XB_STR + h;
#pragma unroll
            for (int i = 0; i < 4; ++i) {
                float4 v = *(const float4*)(src + i * 4);
                v.x = tf32r(v.x); v.y = tf32r(v.y); v.z = tf32r(v.z); v.w = tf32r(v.w);
                *(float4*)(dst + i * 4) = v;
            }
        }
        __syncthreads();

        const float* a0p = Ash + (wm * 32 + g) * XA_STR;
        const float* a1p = a0p + 8 * XA_STR;
        const float* a2p = a0p + 16 * XA_STR;
        const float* a3p = a0p + 24 * XA_STR;
        const float* bp0 = Bsh + (wcol + 0  + g) * XB_STR;
        const float* bp1 = Bsh + (wcol + 8  + g) * XB_STR;
        const float* bp2 = Bsh + (wcol + 16 + g) * XB_STR;
        const float* bp3 = Bsh + (wcol + 24 + g) * XB_STR;

#pragma unroll 4
        for (int kk = 0; kk < 8; ++kk) {
            const int k8 = kk * 8 + tig;
            uint32_t af0[4] = { __float_as_uint(a0p[k8]), __float_as_uint(a1p[k8]),
                                __float_as_uint(a0p[k8 + 4]), __float_as_uint(a1p[k8 + 4]) };
            uint32_t af1[4] = { __float_as_uint(a2p[k8]), __float_as_uint(a3p[k8]),
                                __float_as_uint(a2p[k8 + 4]), __float_as_uint(a3p[k8 + 4]) };
            uint32_t bf0[2] = { __float_as_uint(bp0[k8]), __float_as_uint(bp0[k8 + 4]) };
            uint32_t bf1[2] = { __float_as_uint(bp1[k8]), __float_as_uint(bp1[k8 + 4]) };
            uint32_t bf2[2] = { __float_as_uint(bp2[k8]), __float_as_uint(bp2[k8 + 4]) };
            uint32_t bf3[2] = { __float_as_uint(bp3[k8]), __float_as_uint(bp3[k8 + 4]) };
            mma1688(c[0][0], af0, bf0); mma1688(c[0][1], af0, bf1);
            mma1688(c[0][2], af0, bf2); mma1688(c[0][3], af0, bf3);
            mma1688(c[1][0], af1, bf0); mma1688(c[1][1], af1, bf1);
            mma1688(c[1][2], af1, bf2); mma1688(c[1][3], af1, bf3);
        }
    }

    float2 bias[4];
#pragma unroll
    for (int nf = 0; nf < 4; ++nf) {
        int col = n0 + wcol + nf * 8 + 2 * tig;
        bias[nf].x = bih[col] + bhh[col];
        bias[nf].y = bih[col + 1] + bhh[col + 1];
    }
#pragma unroll
    for (int mf = 0; mf < 2; ++mf) {
#pragma unroll
        for (int rs = 0; rs < 2; ++rs) {
            int grow = m0 + wm * 32 + mf * 16 + g + rs * 8;
            int b = grow >> 9;
            int t = grow & 511;
            float* orow = g_xp + ((size_t)t * B_ + b) * G4_ + n0 + wcol + 2 * tig;
#pragma unroll
            for (int nf = 0; nf < 4; ++nf) {
                float2 v;
                v.x = c[mf][nf][rs * 2 + 0] + bias[nf].x;
                v.y = c[mf][nf][rs * 2 + 1] + bias[nf].y;
                *(float2*)(orow + nf * 8) = v;
            }
        }
    }
}

// =====================================================================
// Kernel 2: persistent recurrence.
//   128 CTAs (4 b-tiles x 32 j-tiles) x 512 threads (16 warps).
//   Warps 0-7 compute: (jgroup jg = wid>>1) x (K-slice ks = wid&1, K=256).
//     Warp tile: M=32 (full b-tile), N=16 = 4 j x 4 gates, LDS.128 frag loads.
//   Warps 8-15: stage h_prev (paired layout, cp.async.cg).
//   Cell: 512 threads, each owns one (b, j); c-state 1 reg.
//   Paired layout pos(k) = (k>>4)*16 + (k&3)*4 + ((k>>2)&1) + 2*((k>>3)&1)
//   -> float4 at [blk*16 + tq*4] holds k = blk*16 + {tq, tq+4, tq+8, tq+12}.
// =====================================================================
#define WSTR 528                      // Wsh/Hsh row stride (floats): 16 mod 32 -> conflict-free
#define NP 72                         // partial row stride
#define HSH_OFF (64 * WSTR)
#define PSH_OFF (96 * WSTR)
#define REC_SMEM ((96 * WSTR + 2 * 32 * NP) * 4)

__global__ void __launch_bounds__(512, 1) lstm_rec_mma(
    const float* __restrict__ Whh,   // [4H, H]
    float* __restrict__ out)         // [T*B, H]
{
    extern __shared__ float sm[];
    float* Wsh = sm;                  // [64 n][528] paired
    float* Hsh = sm + HSH_OFF;        // [32 b][528] paired
    float* Psh = sm + PSH_OFF;        // [2 ks][32 b][72]
    const uint32_t sb = smem_u32(sm);

    const int tid  = threadIdx.x;
    const int wid  = tid >> 5;
    const int lane = tid & 31;
    const int g    = lane >> 2;       // 0..7
    const int tq   = lane & 3;        // 0..3
    const int bt = blockIdx.x >> 5;
    const int jt = blockIdx.x & 31;
    const int b0 = bt * 32;
    const int j0 = jt * 16;

    // ---- one-time: prepack W_hh slice into paired SMEM ----
    // Wsh row n: gate=(n>>2)&3, jl=(n>>4)*4+(n&3)  (warp jg's B rows = jg*16+f*8+g)
    {
        int n    = tid >> 3;
        int kseg = (tid & 7) * 64;
        int gate = (n >> 2) & 3;
        int jl   = (n >> 4) * 4 + (n & 3);
        const float* src = Whh + (size_t)(gate * H_ + j0 + jl) * H_ + kseg;
        float* dst = Wsh + n * WSTR;
#pragma unroll 4
        for (int k = 0; k < 64; k += 4) {
            float4 v = *(const float4*)(src + k);
            int ka  = kseg + k;
            int blk = (ka >> 4) * 16;
            int e   = ((ka >> 2) & 1) + 2 * ((ka >> 3) & 1);
            dst[blk + 0  + e] = tf32r(v.x);
            dst[blk + 4  + e] = tf32r(v.y);
            dst[blk + 8  + e] = tf32r(v.z);
            dst[blk + 12 + e] = tf32r(v.w);
        }
    }
    __syncthreads();

    const int jg = wid >> 1;          // compute warps: j-group 0..3
    const int ks = wid & 1;           // K-slice 0..1
    const int kbase = ks * 256;

    const int cb = tid >> 4;          // cell ownership: b row 0..31
    const int cj = tid & 15;          // j 0..15
    const int nloc = (cj >> 2) * 16 + (cj & 3);   // partial col base for gate q: +q*4
    const int hpos = jt * 16 + (cj & 3) * 4 + ((cj >> 2) & 1) + 2 * ((cj >> 3) & 1);
    float c_state = 0.f;

    for (int t = 0; t < T_; ++t) {
        // ---- stagers: copy h_{t-1} rows (paired layout, L1-bypass) ----
        if (wid >= 8 && t > 0) {
            int s   = tid - 256;              // 0..255
            int b   = s >> 3;
            int seg = (s & 7) * 64;
            const float* src = g_h[(t - 1) & 1] + (size_t)(b0 + b) * 512 + seg;
            uint32_t dst = sb + (uint32_t)(HSH_OFF + b * WSTR + seg) * 4;
#pragma unroll
            for (int i = 0; i < 16; ++i)
                asm volatile("cp.async.cg.shared.global [%0], [%1], 16;"
                             :: "r"(dst + i * 16), "l"(src + i * 4));
            asm volatile("cp.async.commit_group;" ::: "memory");
            asm volatile("cp.async.wait_group 0;" ::: "memory");
        }

        // ---- xp prefetch (all threads; consumed at cell) ----
        float xp[4];
        {
            const float* p = g_xp + ((size_t)t * B_ + b0 + cb) * G4_ + j0 + cj;
#pragma unroll
            for (int q = 0; q < 4; ++q) xp[q] = __ldg(p + q * 512);
        }
        __syncthreads();

        // ---- compute warps: mma over K slice ----
        if (wid < 8 && t > 0) {
            float acc[2][2][4];
#pragma unroll
            for (int m = 0; m < 2; ++m)
#pragma unroll
                for (int f = 0; f < 2; ++f)
#pragma unroll
                    for (int i = 0; i < 4; ++i) acc[m][f][i] = 0.f;

            const float* Ab = Hsh + tq * 4;
            const float* Bb = Wsh + (jg * 16 + g) * WSTR + tq * 4;
#pragma unroll 2
            for (int z = 0; z < 16; ++z) {
                const int ko = kbase + z * 16;
                float4 a4[4];
#pragma unroll
                for (int r = 0; r < 4; ++r)
                    a4[r] = *(const float4*)(Ab + (g + 8 * r) * WSTR + ko);
                float4 b4[2];
#pragma unroll
                for (int f = 0; f < 2; ++f)
                    b4[f] = *(const float4*)(Bb + f * 8 * WSTR + ko);
#pragma unroll
                for (int s2 = 0; s2 < 2; ++s2) {
#pragma unroll
                    for (int m = 0; m < 2; ++m) {
                        uint32_t aa[4] = {
                            __float_as_uint(fcomp(a4[2 * m],     2 * s2)),
                            __float_as_uint(fcomp(a4[2 * m + 1], 2 * s2)),
                            __float_as_uint(fcomp(a4[2 * m],     2 * s2 + 1)),
                            __float_as_uint(fcomp(a4[2 * m + 1], 2 * s2 + 1)) };
#pragma unroll
                        for (int f = 0; f < 2; ++f) {
                            uint32_t bb[2] = {
                                __float_as_uint(fcomp(b4[f], 2 * s2)),
                                __float_as_uint(fcomp(b4[f], 2 * s2 + 1)) };
                            mma1688(acc[m][f], aa, bb);
                        }
                    }
                }
            }
            // store partials
            float* P = Psh + ks * 32 * NP;
#pragma unroll
            for (int m = 0; m < 2; ++m)
#pragma unroll
                for (int f = 0; f < 2; ++f) {
                    float2 v0; v0.x = acc[m][f][0]; v0.y = acc[m][f][1];
                    float2 v1; v1.x = acc[m][f][2]; v1.y = acc[m][f][3];
                    *(float2*)(P + (m * 16 + g)     * NP + jg * 16 + f * 8 + 2 * tq) = v0;
                    *(float2*)(P + (m * 16 + 8 + g) * NP + jg * 16 + f * 8 + 2 * tq) = v1;
                }
        }
        __syncthreads();

        // ---- cell: one (b, j) per thread ----
        {
            const float* P0 = Psh + cb * NP + nloc;
            const float* P1 = P0 + 32 * NP;
            float gs[4];
#pragma unroll
            for (int q = 0; q < 4; ++q) {
                float v = xp[q];
                if (t > 0) v += P0[q * 4] + P1[q * 4];
                gs[q] = v;
            }
            float i_s = 1.f / (1.f + __expf(-gs[0]));
            float f_s = 1.f / (1.f + __expf(-gs[1]));
            float g_t = tanhf(gs[2]);
            float o_s = 1.f / (1.f + __expf(-gs[3]));
            float cv  = f_s * c_state + i_s * g_t;
            c_state   = cv;
            float hv  = o_s * tanhf(cv);

            out[((size_t)t * B_ + b0 + cb) * H_ + j0 + cj] = hv;
            g_h[t & 1][(size_t)(b0 + cb) * 512 + hpos] = tf32r(hv);
        }

        grid_barrier(t, 128u);
    }
}

// =====================================================================
extern "C" void kernel_launch(void* const* d_in, const int* in_sizes, int n_in,
                              void* d_out, int out_size)
{
    const float* x   = (const float*)d_in[0];   // [B,T,D]
    const float* Wih = (const float*)d_in[1];   // [4H,D]
    const float* Whh = (const float*)d_in[2];   // [4H,H]
    const float* bih = (const float*)d_in[3];   // [4H]
    const float* bhh = (const float*)d_in[4];   // [4H]
    float* out = (float*)d_out;

    cudaFuncSetAttribute(xproj_mma,
                         cudaFuncAttributeMaxDynamicSharedMemorySize, XP_SMEM);
    xproj_mma<<<16384, 256, XP_SMEM>>>(x, Wih, bih, bhh);

    cudaFuncSetAttribute(lstm_rec_mma,
                         cudaFuncAttributeMaxDynamicSharedMemorySize, REC_SMEM);
    lstm_rec_mma<<<128, 512, REC_SMEM>>>(Whh, out);
}

// round 7
// speedup vs baseline: 1.3234x; 1.0007x over previous
#include <cuda_runtime.h>
#include <math.h>
#include <cstdint>

#define B_   128
#define T_   512
#define D_   256
#define H_   512
#define G4_  2048   // 4*H

// ---- static device scratch ----
__device__ float g_xp[(size_t)T_ * B_ * G4_];   // [T*B, 4H] x-projections (+biases)
__device__ float g_h[2][B_ * H_];               // ping-pong h, paired-fragment global layout
__device__ unsigned g_cntB[128];                // 4 bt-barriers, padded 32 apart
__device__ volatile unsigned g_genB[128];

// =====================================================================
// helpers
// =====================================================================
__device__ __forceinline__ float tf32r(float x) {
    float y; asm("cvt.rna.tf32.f32 %0, %1;" : "=f"(y) : "f"(x)); return y;
}
__device__ __forceinline__ uint32_t smem_u32(const void* p) {
    uint32_t a;
    asm("{ .reg .u64 t; cvta.to.shared.u64 t, %1; cvt.u32.u64 %0, t; }" : "=r"(a) : "l"(p));
    return a;
}
__device__ __forceinline__ void mma1688(float* c, const uint32_t* a, const uint32_t* b) {
    asm volatile(
        "mma.sync.aligned.m16n8k8.row.col.f32.tf32.tf32.f32 "
        "{%0,%1,%2,%3}, {%4,%5,%6,%7}, {%8,%9}, {%0,%1,%2,%3};"
        : "+f"(c[0]), "+f"(c[1]), "+f"(c[2]), "+f"(c[3])
        : "r"(a[0]), "r"(a[1]), "r"(a[2]), "r"(a[3]), "r"(b[0]), "r"(b[1]));
}
__device__ __forceinline__ float fcomp(const float4& v, int i) {
    return i == 0 ? v.x : (i == 1 ? v.y : (i == 2 ? v.z : v.w));
}
__device__ __forceinline__ void grid_barrier_bt(int step, int bt)
{
    __syncthreads();
    if (threadIdx.x == 0) {
        unsigned next = (unsigned)((step + 1) & (T_ - 1));
        __threadfence();
        unsigned old = atomicAdd(&g_cntB[bt * 32], 1u);
        if (old == 31u) {
            g_cntB[bt * 32] = 0;
            __threadfence();
            g_genB[bt * 32] = next;
        } else {
            while (g_genB[bt * 32] != next) { }
        }
        __threadfence();
    }
    __syncthreads();
}

// =====================================================================
// Kernel 1: x_proj GEMM via tf32 mma (round-3 proven version)
// =====================================================================
#define XA_STR 68
#define XB_STR 68
#define XP_SMEM ((128 * XA_STR + 64 * XB_STR) * 4)

__global__ void __launch_bounds__(256, 1) xproj_mma(
    const float* __restrict__ x,     // [B*T, D]
    const float* __restrict__ Wih,   // [4H, D]
    const float* __restrict__ bih,
    const float* __restrict__ bhh)
{
    extern __shared__ float sm[];
    float* Ash = sm;                   // [128][68]
    float* Bsh = sm + 128 * XA_STR;    // [64][68]

    const int tid  = threadIdx.x;
    const int wid  = tid >> 5;
    const int lane = tid & 31;
    const int g    = lane >> 2;
    const int tig  = lane & 3;
    const int wm   = wid & 3;
    const int wcol = (wid >> 2) * 32;

    const int mt = blockIdx.x >> 5;
    const int nt = blockIdx.x & 31;
    const int m0 = mt * 128;
    const int n0 = nt * 64;

    float c[2][4][4];
#pragma unroll
    for (int a = 0; a < 2; ++a)
#pragma unroll
        for (int b = 0; b < 4; ++b)
#pragma unroll
            for (int i = 0; i < 4; ++i) c[a][b][i] = 0.f;

    for (int kc = 0; kc < 4; ++kc) {
        const int k0 = kc * 64;
        __syncthreads();
        {
            int row = tid >> 1;
            int h   = (tid & 1) * 32;
            const float* src = x + (size_t)(m0 + row) * D_ + k0 + h;
            float* dst = Ash + row * XA_STR + h;
#pragma unroll
            for (int i = 0; i < 8; ++i) {
                float4 v = *(const float4*)(src + i * 4);
                v.x = tf32r(v.x); v.y = tf32r(v.y); v.z = tf32r(v.z); v.w = tf32r(v.w);
                *(float4*)(dst + i * 4) = v;
            }
        }
        {
            int n = tid >> 2;
            int h = (tid & 3) * 16;
            const float* src = Wih + (size_t)(n0 + n) * D_ + k0 + h;
            float* dst = Bsh + n * XB_STR + h;
#pragma unroll
            for (int i = 0; i < 4; ++i) {
                float4 v = *(const float4*)(src + i * 4);
                v.x = tf32r(v.x); v.y = tf32r(v.y); v.z = tf32r(v.z); v.w = tf32r(v.w);
                *(float4*)(dst + i * 4) = v;
            }
        }
        __syncthreads();

        const float* a0p = Ash + (wm * 32 + g) * XA_STR;
        const float* a1p = a0p + 8 * XA_STR;
        const float* a2p = a0p + 16 * XA_STR;
        const float* a3p = a0p + 24 * XA_STR;
        const float* bp0 = Bsh + (wcol + 0  + g) * XB_STR;
        const float* bp1 = Bsh + (wcol + 8  + g) * XB_STR;
        const float* bp2 = Bsh + (wcol + 16 + g) * XB_STR;
        const float* bp3 = Bsh + (wcol + 24 + g) * XB_STR;

#pragma unroll 4
        for (int kk = 0; kk < 8; ++kk) {
            const int k8 = kk * 8 + tig;
            uint32_t af0[4] = { __float_as_uint(a0p[k8]), __float_as_uint(a1p[k8]),
                                __float_as_uint(a0p[k8 + 4]), __float_as_uint(a1p[k8 + 4]) };
            uint32_t af1[4] = { __float_as_uint(a2p[k8]), __float_as_uint(a3p[k8]),
                                __float_as_uint(a2p[k8 + 4]), __float_as_uint(a3p[k8 + 4]) };
            uint32_t bf0[2] = { __float_as_uint(bp0[k8]), __float_as_uint(bp0[k8 + 4]) };
            uint32_t bf1[2] = { __float_as_uint(bp1[k8]), __float_as_uint(bp1[k8 + 4]) };
            uint32_t bf2[2] = { __float_as_uint(bp2[k8]), __float_as_uint(bp2[k8 + 4]) };
            uint32_t bf3[2] = { __float_as_uint(bp3[k8]), __float_as_uint(bp3[k8 + 4]) };
            mma1688(c[0][0], af0, bf0); mma1688(c[0][1], af0, bf1);
            mma1688(c[0][2], af0, bf2); mma1688(c[0][3], af0, bf3);
            mma1688(c[1][0], af1, bf0); mma1688(c[1][1], af1, bf1);
            mma1688(c[1][2], af1, bf2); mma1688(c[1][3], af1, bf3);
        }
    }

    float2 bias[4];
#pragma unroll
    for (int nf = 0; nf < 4; ++nf) {
        int col = n0 + wcol + nf * 8 + 2 * tig;
        bias[nf].x = bih[col] + bhh[col];
        bias[nf].y = bih[col + 1] + bhh[col + 1];
    }
#pragma unroll
    for (int mf = 0; mf < 2; ++mf) {
#pragma unroll
        for (int rs = 0; rs < 2; ++rs) {
            int grow = m0 + wm * 32 + mf * 16 + g + rs * 8;
            int b = grow >> 9;
            int t = grow & 511;
            float* orow = g_xp + ((size_t)t * B_ + b) * G4_ + n0 + wcol + 2 * tig;
#pragma unroll
            for (int nf = 0; nf < 4; ++nf) {
                float2 v;
                v.x = c[mf][nf][rs * 2 + 0] + bias[nf].x;
                v.y = c[mf][nf][rs * 2 + 1] + bias[nf].y;
                *(float2*)(orow + nf * 8) = v;
            }
        }
    }
}

// =====================================================================
// Kernel 2: persistent recurrence v3.
//   128 CTAs (4 bt x 32 jt) x 512 threads.
//   Warps 0-7 compute: jg = wid&1 (N=32), ks = wid>>1 (K=128).
//   Warps 8-15 stage h_prev in 2 halves (named-barrier overlap with mma).
//   Wsh/Hsh: stride 512 floats + 16-float-block XOR swizzle (key = row&7).
//   Within 16-block, paired order pos(k) = (k&3)*4 + ((k>>2)&1) + 2*((k>>3)&1)
//   -> float4 at [tq*4] holds k = {tq, tq+4, tq+8, tq+12}.
//   4 partial K-slices reduced in the cell (512 threads, 1 (b,j) each).
// =====================================================================
#define HSH_OFF 32768                 // floats: after Wsh 64*512
#define PSH_OFF 49152                 // floats: after Hsh 32*512
#define NP 68                         // partial row stride
#define PSLICE (32 * NP)
#define REC_SMEM ((PSH_OFF + 4 * PSLICE) * 4)   // 231424 B

__global__ void __launch_bounds__(512, 1) lstm_rec_mma(
    const float* __restrict__ Whh,   // [4H, H]
    float* __restrict__ out)         // [T*B, H]
{
    extern __shared__ float sm[];
    float* Wsh = sm;                  // [64 n][512] swizzled+paired
    float* Hsh = sm + HSH_OFF;        // [32 b][512] swizzled+paired
    float* Psh = sm + PSH_OFF;        // [4 ks][32 b][68]
    const uint32_t sb = smem_u32(sm);

    const int tid  = threadIdx.x;
    const int wid  = tid >> 5;
    const int lane = tid & 31;
    const int g    = lane >> 2;       // 0..7
    const int tq   = lane & 3;        // 0..3
    const int bt = blockIdx.x >> 5;
    const int jt = blockIdx.x & 31;
    const int b0 = bt * 32;
    const int j0 = jt * 16;

    // ---- one-time: prepack W_hh slice into swizzled paired SMEM ----
    // Wsh row n: gate=(n>>2)&3, jl=(n>>4)*4+(n&3)
    {
        int n    = tid >> 3;          // 0..63
        int kseg = (tid & 7) * 64;
        int gate = (n >> 2) & 3;
        int jl   = (n >> 4) * 4 + (n & 3);
        int key  = n & 7;
        const float* src = Whh + (size_t)(gate * H_ + j0 + jl) * H_ + kseg;
        float* dst = Wsh + n * 512;
#pragma unroll 4
        for (int k = 0; k < 64; k += 4) {
            float4 v = *(const float4*)(src + k);
            int ka  = kseg + k;
            int base = (((ka >> 4) ^ key) << 4);
            int e   = ((ka >> 2) & 1) + 2 * ((ka >> 3) & 1);
            dst[base + 0  + e] = tf32r(v.x);
            dst[base + 4  + e] = tf32r(v.y);
            dst[base + 8  + e] = tf32r(v.z);
            dst[base + 12 + e] = tf32r(v.w);
        }
    }
    __syncthreads();

    const int jg = wid & 1;           // compute: N-group (cols jg*32..+32)
    const int ks = wid >> 1;          // compute: K-slice 0..3 (warps 0-7)
    const int half = ks >> 1;         // staging half this warp consumes

    // cell ownership: one (b, j) per thread
    const int cb = tid >> 4;          // 0..31
    const int cj = tid & 15;          // 0..15
    const int nloc = ((cj >> 2) << 4) + (cj & 3);
    const int hpos = jt * 16 + (cj & 3) * 4 + ((cj >> 2) & 1) + 2 * ((cj >> 3) & 1);
    float c_state = 0.f;

    // xp prefetch for t=0
    float xp[4];
    {
        const float* p = g_xp + ((size_t)0 * B_ + b0 + cb) * G4_ + j0 + cj;
#pragma unroll
        for (int q = 0; q < 4; ++q) xp[q] = p[q * 512];
    }

    // stager constants (warps 8-15)
    const int ss   = tid - 256;       // 0..255 when wid>=8
    const int shalf = (ss >> 7) & 1;
    const int srow  = (ss & 127) >> 2;
    const int sc0   = shalf * 256 + (ss & 3) * 64;
    const int skey  = srow & 7;

    for (int t = 0; t < T_; ++t) {
        if (t > 0) {
            if (wid >= 8) {
                // ---- stage own half of h_{t-1} (swizzled dst) ----
                const float* src = g_h[(t - 1) & 1] + (size_t)(b0 + srow) * 512 + sc0;
                uint32_t dbase = sb + (uint32_t)(HSH_OFF + srow * 512) * 4;
#pragma unroll
                for (int i = 0; i < 16; ++i) {
                    int k   = sc0 + 4 * i;
                    int off = (((k >> 4) ^ skey) << 4) + (k & 15);
                    asm volatile("cp.async.cg.shared.global [%0], [%1], 16;"
                                 :: "r"(dbase + (uint32_t)off * 4), "l"(src + 4 * i));
                }
                asm volatile("cp.async.commit_group;" ::: "memory");
                asm volatile("cp.async.wait_group 0;" ::: "memory");
                __threadfence_block();
                if (shalf == 0) asm volatile("bar.arrive 1, 256;");
                else            asm volatile("bar.arrive 2, 256;");
            } else {
                // ---- compute: wait for my half, then mma over K=128 slice ----
                if (half == 0) asm volatile("bar.sync 1, 256;");
                else           asm volatile("bar.sync 2, 256;");

                float acc[2][4][4];
#pragma unroll
                for (int m = 0; m < 2; ++m)
#pragma unroll
                    for (int f = 0; f < 4; ++f)
#pragma unroll
                        for (int i = 0; i < 4; ++i) acc[m][f][i] = 0.f;

                const float* Ha = Hsh + g * 512 + tq * 4;
                const float* Wb = Wsh + (jg * 32 + g) * 512 + tq * 4;
#pragma unroll 2
                for (int z = 0; z < 8; ++z) {
                    const int offz = (((ks * 8 + z) ^ g) << 4);
                    float4 a4[4];
#pragma unroll
                    for (int r = 0; r < 4; ++r)
                        a4[r] = *(const float4*)(Ha + r * 8 * 512 + offz);
                    float4 b4[4];
#pragma unroll
                    for (int f = 0; f < 4; ++f)
                        b4[f] = *(const float4*)(Wb + f * 8 * 512 + offz);
#pragma unroll
                    for (int s2 = 0; s2 < 2; ++s2) {
#pragma unroll
                        for (int m = 0; m < 2; ++m) {
                            uint32_t aa[4] = {
                                __float_as_uint(fcomp(a4[2 * m],     2 * s2)),
                                __float_as_uint(fcomp(a4[2 * m + 1], 2 * s2)),
                                __float_as_uint(fcomp(a4[2 * m],     2 * s2 + 1)),
                                __float_as_uint(fcomp(a4[2 * m + 1], 2 * s2 + 1)) };
#pragma unroll
                            for (int f = 0; f < 4; ++f) {
                                uint32_t bb[2] = {
                                    __float_as_uint(fcomp(b4[f], 2 * s2)),
                                    __float_as_uint(fcomp(b4[f], 2 * s2 + 1)) };
                                mma1688(acc[m][f], aa, bb);
                            }
                        }
                    }
                }
                // partial store: slice ks
                float* P = Psh + ks * PSLICE;
#pragma unroll
                for (int m = 0; m < 2; ++m)
#pragma unroll
                    for (int f = 0; f < 4; ++f) {
                        int col = jg * 32 + f * 8 + 2 * tq;
                        float2 v0; v0.x = acc[m][f][0]; v0.y = acc[m][f][1];
                        float2 v1; v1.x = acc[m][f][2]; v1.y = acc[m][f][3];
                        *(float2*)(P + (m * 16 + g)     * NP + col) = v0;
                        *(float2*)(P + (m * 16 + 8 + g) * NP + col) = v1;
                    }
            }
        }
        __syncthreads();

        // prefetch xp for t+1 (consumed next iteration, hidden behind cell+barrier)
        float xpn[4];
        if (t + 1 < T_) {
            const float* p = g_xp + ((size_t)(t + 1) * B_ + b0 + cb) * G4_ + j0 + cj;
#pragma unroll
            for (int q = 0; q < 4; ++q) xpn[q] = p[q * 512];
        }

        // ---- cell ----
        {
            float gs[4];
#pragma unroll
            for (int q = 0; q < 4; ++q) gs[q] = xp[q];
            if (t > 0) {
#pragma unroll
                for (int s = 0; s < 4; ++s) {
                    const float* Ps = Psh + s * PSLICE + cb * NP + nloc;
#pragma unroll
                    for (int q = 0; q < 4; ++q) gs[q] += Ps[q * 4];
                }
            }
            float i_s = 1.f / (1.f + __expf(-gs[0]));
            float f_s = 1.f / (1.f + __expf(-gs[1]));
            float g_t = tanhf(gs[2]);
            float o_s = 1.f / (1.f + __expf(-gs[3]));
            float cv  = f_s * c_state + i_s * g_t;
            c_state   = cv;
            float hv  = o_s * tanhf(cv);

            out[((size_t)t * B_ + b0 + cb) * H_ + j0 + cj] = hv;
            g_h[t & 1][(size_t)(b0 + cb) * 512 + hpos] = tf32r(hv);
        }
#pragma unroll
        for (int q = 0; q < 4; ++q) xp[q] = xpn[q];

        grid_barrier_bt(t, bt);
    }
}

// =====================================================================
extern "C" void kernel_launch(void* const* d_in, const int* in_sizes, int n_in,
                              void* d_out, int out_size)
{
    const float* x   = (const float*)d_in[0];   // [B,T,D]
    const float* Wih = (const float*)d_in[1];   // [4H,D]
    const float* Whh = (const float*)d_in[2];   // [4H,H]
    const float* bih = (const float*)d_in[3];   // [4H]
    const float* bhh = (const float*)d_in[4];   // [4H]
    float* out = (float*)d_out;

    cudaFuncSetAttribute(xproj_mma,
                         cudaFuncAttributeMaxDynamicSharedMemorySize, XP_SMEM);
    xproj_mma<<<16384, 256, XP_SMEM>>>(x, Wih, bih, bhh);

    cudaFuncSetAttribute(lstm_rec_mma,
                         cudaFuncAttributeMaxDynamicSharedMemorySize, REC_SMEM);
    lstm_rec_mma<<<128, 512, REC_SMEM>>>(Whh, out);
}